// round 2
// baseline (speedup 1.0000x reference)
#include <cuda_runtime.h>
#include <math.h>

// Problem constants
#define T_      80
#define BS_     8
#define DM_     768
#define H_      4
#define DH_     192
#define FF_     1024
#define L_      4
#define LATENT_ 256
#define ROWS_   (T_ * BS_)      // 640
#define NJF_    150
#define A_      6

#define EPS_ATT 1e-6f
#define EPS_LN  1e-5f

// ---------------------------------------------------------------------------
// Scratch (no cudaMalloc allowed) — referenced directly from device code,
// so kernel_launch contains NOTHING but kernel launches.
// ---------------------------------------------------------------------------
__device__ float g_h  [ROWS_ * DM_];
__device__ float g_h1 [ROWS_ * DM_];
__device__ float g_q  [ROWS_ * DM_];
__device__ float g_k  [ROWS_ * DM_];
__device__ float g_v  [ROWS_ * DM_];
__device__ float g_att[ROWS_ * DM_];
__device__ float g_ff [ROWS_ * FF_];

#define BUF_H   0
#define BUF_H1  1
#define BUF_Q   2
#define BUF_K   3
#define BUF_V   4
#define BUF_ATT 5
#define BUF_FF  6

__device__ __forceinline__ float* scratch(int code)
{
    switch (code) {
        case BUF_H:   return g_h;
        case BUF_H1:  return g_h1;
        case BUF_Q:   return g_q;
        case BUF_K:   return g_k;
        case BUF_V:   return g_v;
        case BUF_ATT: return g_att;
        default:      return g_ff;
    }
}

// ---------------------------------------------------------------------------
// h0: skeleton embedding + mu/sigma query gather + positional encoding
// one block per row (t,b); 256 threads
// ---------------------------------------------------------------------------
__global__ void build_h0_kernel(const float* __restrict__ x,        // [bs,25,6,T]
                                const int*   __restrict__ y,        // [bs,A]
                                const int*   __restrict__ ind_map,  // [T,bs]
                                const float* __restrict__ skW,      // [150,256]
                                const float* __restrict__ skb,      // [256]
                                const float* __restrict__ muQ,      // [C,256]
                                const float* __restrict__ sgQ)      // [C,256]
{
    const int r = blockIdx.x;
    const int t = r / BS_;
    const int b = r - t * BS_;
    const int tid = threadIdx.x;          // 0..255

    __shared__ float xrow[NJF_];
    if (tid < NJF_) xrow[tid] = x[(size_t)b * NJF_ * T_ + tid * T_ + t];
    __syncthreads();

    const int a   = ind_map[t * BS_ + b];
    const int cls = y[b * A_ + a];
    const int start = (t == 0) ? 0 : (t + 2);

    // positional encoding factor for this channel-within-segment
    const float div = expf(-(logf(10000.0f) / (float)LATENT_) * (float)(tid & ~1));
    const bool  odd = (tid & 1);

    float base0 = muQ[cls * LATENT_ + tid];
    float base1 = sgQ[cls * LATENT_ + tid];
    float acc = skb[tid];
    #pragma unroll 5
    for (int jf = 0; jf < NJF_; jf++) acc += xrow[jf] * skW[jf * LATENT_ + tid];

    float* dst = g_h + (size_t)r * DM_;
    {
        float ang = (float)(start + 0) * div;
        dst[tid]             = base0 + (odd ? cosf(ang) : sinf(ang));
    }
    {
        float ang = (float)(start + 1) * div;
        dst[tid + LATENT_]   = base1 + (odd ? cosf(ang) : sinf(ang));
    }
    {
        float ang = (float)(start + 2) * div;
        dst[tid + 2*LATENT_] = acc   + (odd ? cosf(ang) : sinf(ang));
    }
}

// ---------------------------------------------------------------------------
// Generic fp32 SIMT GEMM tile body: 64x64x16, 256 threads, 4x4 per thread
// act: 0 = none, 1 = elu(x)+1, 2 = relu
// ---------------------------------------------------------------------------
#define GBM 64
#define GBN 64
#define GBK 16

__device__ __forceinline__ void gemm_tile_body(const float* __restrict__ A,
                                               const float* __restrict__ B,
                                               const float* __restrict__ bias,
                                               float* __restrict__ C,
                                               int N, int K,
                                               int rowBase, int colBase, int act)
{
    __shared__ float As[GBM][20];   // padded (20 floats); rows stay 16B aligned
    __shared__ float Bs[GBK][GBN];

    const int tid = threadIdx.x;
    const int tx  = tid & 15;
    const int ty  = tid >> 4;

    float acc[4][4] = {};

    for (int k0 = 0; k0 < K; k0 += GBK) {
        {
            int r  = tid >> 2;
            int c4 = (tid & 3) << 2;
            float4 av = *(const float4*)(A + (size_t)(rowBase + r) * K + k0 + c4);
            *(float4*)&As[r][c4] = av;
        }
        {
            int r  = tid >> 4;
            int c4 = (tid & 15) << 2;
            float4 bv = *(const float4*)(B + (size_t)(k0 + r) * N + colBase + c4);
            *(float4*)&Bs[r][c4] = bv;
        }
        __syncthreads();

        #pragma unroll
        for (int kk = 0; kk < GBK; kk++) {
            float a0 = As[ty*4+0][kk];
            float a1 = As[ty*4+1][kk];
            float a2 = As[ty*4+2][kk];
            float a3 = As[ty*4+3][kk];
            float4 bv = *(const float4*)&Bs[kk][tx*4];
            acc[0][0] += a0*bv.x; acc[0][1] += a0*bv.y; acc[0][2] += a0*bv.z; acc[0][3] += a0*bv.w;
            acc[1][0] += a1*bv.x; acc[1][1] += a1*bv.y; acc[1][2] += a1*bv.z; acc[1][3] += a1*bv.w;
            acc[2][0] += a2*bv.x; acc[2][1] += a2*bv.y; acc[2][2] += a2*bv.z; acc[2][3] += a2*bv.w;
            acc[3][0] += a3*bv.x; acc[3][1] += a3*bv.y; acc[3][2] += a3*bv.z; acc[3][3] += a3*bv.w;
        }
        __syncthreads();
    }

    #pragma unroll
    for (int i = 0; i < 4; i++) {
        int r = rowBase + ty*4 + i;
        #pragma unroll
        for (int j = 0; j < 4; j++) {
            int c = colBase + tx*4 + j;
            float v = acc[i][j] + bias[c];
            if (act == 1)      v = (v > 0.0f) ? (v + 1.0f) : expf(v);  // elu + 1
            else if (act == 2) v = fmaxf(v, 0.0f);                     // relu
            C[(size_t)r * N + c] = v;
        }
    }
}

__global__ void gemm_kernel(int a_code, const float* __restrict__ B,
                            const float* __restrict__ bias, int c_code,
                            int N, int K, int act)
{
    gemm_tile_body(scratch(a_code), B, bias, scratch(c_code),
                   N, K, blockIdx.y * GBM, blockIdx.x * GBN, act);
}

// Fused QKV: virtual N = 3*768; each 64-col block belongs to exactly one matrix
__global__ void gemm_qkv_kernel(const float* __restrict__ Wq, const float* __restrict__ Wk,
                                const float* __restrict__ Wv,
                                const float* __restrict__ bq, const float* __restrict__ bk,
                                const float* __restrict__ bv)
{
    const int gcol = blockIdx.x * GBN;
    const int mat  = gcol / DM_;
    const int colBase = gcol - mat * DM_;
    const float* B    = (mat == 0) ? Wq  : (mat == 1) ? Wk  : Wv;
    const float* bias = (mat == 0) ? bq  : (mat == 1) ? bk  : bv;
    float*       C    = (mat == 0) ? g_q : (mat == 1) ? g_k : g_v;
    const int act     = (mat < 2) ? 1 : 0;   // elu+1 on Q,K; none on V
    gemm_tile_body(g_h, B, bias, C, DM_, DM_, blockIdx.y * GBM, colBase, act);
}

// ---------------------------------------------------------------------------
// Causal linear attention, one block per (b,h). Static smem only (25.9 KB).
// att_t = ( sum_{tau<=t} (Q_t.K_tau) v_tau ) / ( sum_{tau<=t} Q_t.K_tau + eps )
// ---------------------------------------------------------------------------
__global__ void attn_kernel()
{
    __shared__ float Asc[T_ * T_];        // score matrix (zeros above diagonal)
    __shared__ float inv[T_];

    const int bh = blockIdx.x;
    const int b  = bh >> 2;
    const int h  = bh & 3;
    const int tid = threadIdx.x;
    const int nth = blockDim.x;

    // scores
    for (int p = tid; p < T_ * T_; p += nth) {
        int t = p / T_, tau = p - t * T_;
        float s = 0.0f;
        if (tau <= t) {
            const float* qp = g_q + (size_t)(t   * BS_ + b) * DM_ + h * DH_;
            const float* kp = g_k + (size_t)(tau * BS_ + b) * DM_ + h * DH_;
            #pragma unroll 8
            for (int d = 0; d < DH_; d++) s += qp[d] * kp[d];
        }
        Asc[p] = s;
    }
    __syncthreads();

    // 1 / (causal row-sum + eps)
    for (int t = tid; t < T_; t += nth) {
        float s = 0.0f;
        for (int tau = 0; tau <= t; tau++) s += Asc[t * T_ + tau];
        inv[t] = 1.0f / (s + EPS_ATT);
    }
    __syncthreads();

    // att = (A V) * inv   (coalesced over d across lanes)
    for (int p = tid; p < T_ * DH_; p += nth) {
        int t = p / DH_, d = p - t * DH_;
        const float* ar = Asc + t * T_;
        float acc = 0.0f;
        for (int tau = 0; tau <= t; tau++)
            acc += ar[tau] * g_v[(size_t)(tau * BS_ + b) * DM_ + h * DH_ + d];
        g_att[(size_t)(t * BS_ + b) * DM_ + h * DH_ + d] = acc * inv[t];
    }
}

// ---------------------------------------------------------------------------
// LayerNorm(x + y) * g + b  — one block per row, 256 threads (3 ch each)
// ---------------------------------------------------------------------------
__device__ __forceinline__ float block_sum_256(float val)
{
    __shared__ float sh[8];
    const int lane = threadIdx.x & 31;
    const int w    = threadIdx.x >> 5;
    #pragma unroll
    for (int o = 16; o > 0; o >>= 1) val += __shfl_down_sync(0xffffffffu, val, o);
    if (lane == 0) sh[w] = val;
    __syncthreads();
    if (w == 0) {
        float r = (lane < 8) ? sh[lane] : 0.0f;
        #pragma unroll
        for (int o = 4; o > 0; o >>= 1) r += __shfl_down_sync(0xffffffffu, r, o);
        if (lane == 0) sh[0] = r;
    }
    __syncthreads();
    float res = sh[0];
    __syncthreads();
    return res;
}

__global__ void ln_residual_kernel(int x_code, int y_code,
                                   const float* __restrict__ g, const float* __restrict__ bt,
                                   int out_code)
{
    const float* x  = scratch(x_code);
    const float* yv = scratch(y_code);
    float* out      = scratch(out_code);

    const int row = blockIdx.x;
    const int tid = threadIdx.x;
    const size_t base = (size_t)row * DM_;

    float v0 = x[base + tid]       + yv[base + tid];
    float v1 = x[base + tid + 256] + yv[base + tid + 256];
    float v2 = x[base + tid + 512] + yv[base + tid + 512];

    float mean = block_sum_256(v0 + v1 + v2) * (1.0f / (float)DM_);
    float d0 = v0 - mean, d1 = v1 - mean, d2 = v2 - mean;
    float var = block_sum_256(d0*d0 + d1*d1 + d2*d2) * (1.0f / (float)DM_);
    float rstd = rsqrtf(var + EPS_LN);

    out[base + tid]       = d0 * rstd * g[tid]       + bt[tid];
    out[base + tid + 256] = d1 * rstd * g[tid + 256] + bt[tid + 256];
    out[base + tid + 512] = d2 * rstd * g[tid + 512] + bt[tid + 512];
}

// ---------------------------------------------------------------------------
// Final: gather selected rows, apply final LN, emit mu || logvar
// one block per (b,a) pair — 48 blocks, 256 threads
// ---------------------------------------------------------------------------
__global__ void gather_kernel(const int* __restrict__ act_ts,
                              const float* __restrict__ g, const float* __restrict__ bt,
                              float* __restrict__ out)
{
    const int ba = blockIdx.x;            // b*A + a
    const int b  = ba / A_;
    int t = act_ts[ba] - 1;
    if (t < 0) t = 0;
    const int row = t * BS_ + b;
    const int tid = threadIdx.x;
    const size_t base = (size_t)row * DM_;

    float v0 = g_h[base + tid];
    float v1 = g_h[base + tid + 256];
    float v2 = g_h[base + tid + 512];

    float mean = block_sum_256(v0 + v1 + v2) * (1.0f / (float)DM_);
    float d0 = v0 - mean, d1 = v1 - mean, d2 = v2 - mean;
    float var = block_sum_256(d0*d0 + d1*d1 + d2*d2) * (1.0f / (float)DM_);
    float rstd = rsqrtf(var + EPS_LN);

    // mu = channels [0,256), logvar = channels [256,512)
    out[(size_t)ba * LATENT_ + tid]                      = d0 * rstd * g[tid]       + bt[tid];
    out[(size_t)BS_ * A_ * LATENT_ + ba * LATENT_ + tid] = d1 * rstd * g[tid + 256] + bt[tid + 256];
}

// ---------------------------------------------------------------------------
// Host orchestration: kernel launches ONLY (graph-capture safe)
// ---------------------------------------------------------------------------
extern "C" void kernel_launch(void* const* d_in, const int* in_sizes, int n_in,
                              void* d_out, int out_size)
{
    const float* x    = (const float*)d_in[0];
    const int*   y    = (const int*)  d_in[1];
    const int*   ind  = (const int*)  d_in[2];
    const int*   ats  = (const int*)  d_in[3];
    const float* skW  = (const float*)d_in[4];
    const float* skb  = (const float*)d_in[5];
    const float* muQ  = (const float*)d_in[6];
    const float* sgQ  = (const float*)d_in[7];
    const float* Wq   = (const float*)d_in[8];
    const float* bq   = (const float*)d_in[9];
    const float* Wk   = (const float*)d_in[10];
    const float* bk   = (const float*)d_in[11];
    const float* Wv   = (const float*)d_in[12];
    const float* bv   = (const float*)d_in[13];
    const float* Wo   = (const float*)d_in[14];
    const float* bo   = (const float*)d_in[15];
    const float* W1   = (const float*)d_in[16];
    const float* b1   = (const float*)d_in[17];
    const float* W2   = (const float*)d_in[18];
    const float* b2   = (const float*)d_in[19];
    const float* l1g  = (const float*)d_in[20];
    const float* l1b  = (const float*)d_in[21];
    const float* l2g  = (const float*)d_in[22];
    const float* l2b  = (const float*)d_in[23];
    const float* lfg  = (const float*)d_in[24];
    const float* lfb  = (const float*)d_in[25];
    float* out = (float*)d_out;

    build_h0_kernel<<<ROWS_, 256>>>(x, y, ind, skW, skb, muQ, sgQ);

    const dim3 gQKV(3 * DM_ / GBN, ROWS_ / GBM);   // 36 x 10
    const dim3 g768(DM_ / GBN, ROWS_ / GBM);       // 12 x 10
    const dim3 g1024(FF_ / GBN, ROWS_ / GBM);      // 16 x 10

    for (int l = 0; l < L_; l++) {
        gemm_qkv_kernel<<<gQKV, 256>>>(Wq + (size_t)l * DM_ * DM_,
                                       Wk + (size_t)l * DM_ * DM_,
                                       Wv + (size_t)l * DM_ * DM_,
                                       bq + l * DM_, bk + l * DM_, bv + l * DM_);
        attn_kernel<<<BS_ * H_, 512>>>();
        // O projection (reuse g_q as scratch)
        gemm_kernel<<<g768, 256>>>(BUF_ATT, Wo + (size_t)l * DM_ * DM_, bo + l * DM_,
                                   BUF_Q, DM_, DM_, 0);
        ln_residual_kernel<<<ROWS_, 256>>>(BUF_H, BUF_Q, l1g + l * DM_, l1b + l * DM_, BUF_H1);
        gemm_kernel<<<g1024, 256>>>(BUF_H1, W1 + (size_t)l * DM_ * FF_, b1 + l * FF_,
                                    BUF_FF, FF_, DM_, 2);
        gemm_kernel<<<g768, 256>>>(BUF_FF, W2 + (size_t)l * FF_ * DM_, b2 + l * DM_,
                                   BUF_Q, DM_, FF_, 0);
        ln_residual_kernel<<<ROWS_, 256>>>(BUF_H1, BUF_Q, l2g + l * DM_, l2b + l * DM_, BUF_H);
    }

    gather_kernel<<<BS_ * A_, 256>>>(ats, lfg, lfb, out);
}

// round 4
// speedup vs baseline: 1.9653x; 1.9653x over previous
#include <cuda_runtime.h>
#include <math.h>

// Problem constants
#define T_      80
#define BS_     8
#define DM_     768
#define H_      4
#define DH_     192
#define FF_     1024
#define L_      4
#define LATENT_ 256
#define ROWS_   (T_ * BS_)      // 640
#define NJF_    150
#define A_      6

#define EPS_ATT 1e-6f
#define EPS_LN  1e-5f

// ---------------------------------------------------------------------------
// Scratch — device globals only (no cudaMalloc). Selected device-side via
// small integer codes so kernel_launch is pure kernel launches.
// ---------------------------------------------------------------------------
__device__ float g_h  [ROWS_ * DM_];
__device__ float g_h1 [ROWS_ * DM_];
__device__ float g_q  [ROWS_ * DM_];
__device__ float g_k  [ROWS_ * DM_];
__device__ float g_v  [ROWS_ * DM_];
__device__ float g_att[ROWS_ * DM_];
__device__ float g_ff [ROWS_ * FF_];

#define BUF_H   0
#define BUF_H1  1
#define BUF_Q   2
#define BUF_K   3
#define BUF_V   4
#define BUF_ATT 5
#define BUF_FF  6

__device__ __forceinline__ float* scratch(int code)
{
    switch (code) {
        case BUF_H:   return g_h;
        case BUF_H1:  return g_h1;
        case BUF_Q:   return g_q;
        case BUF_K:   return g_k;
        case BUF_V:   return g_v;
        case BUF_ATT: return g_att;
        default:      return g_ff;
    }
}

// ---------------------------------------------------------------------------
// h0: skeleton embedding + mu/sigma query gather + positional encoding
// ---------------------------------------------------------------------------
__global__ void build_h0_kernel(const float* __restrict__ x,        // [bs,25,6,T]
                                const int*   __restrict__ y,        // [bs,A]
                                const int*   __restrict__ ind_map,  // [T,bs]
                                const float* __restrict__ skW,      // [150,256]
                                const float* __restrict__ skb,      // [256]
                                const float* __restrict__ muQ,      // [C,256]
                                const float* __restrict__ sgQ)      // [C,256]
{
    const int r = blockIdx.x;
    const int t = r / BS_;
    const int b = r - t * BS_;
    const int tid = threadIdx.x;          // 0..255

    __shared__ float xrow[NJF_];
    if (tid < NJF_) xrow[tid] = x[(size_t)b * NJF_ * T_ + tid * T_ + t];
    __syncthreads();

    const int a   = ind_map[t * BS_ + b];
    const int cls = y[b * A_ + a];
    const int start = (t == 0) ? 0 : (t + 2);

    const float div = expf(-(logf(10000.0f) / (float)LATENT_) * (float)(tid & ~1));
    const bool  odd = (tid & 1);

    float base0 = muQ[cls * LATENT_ + tid];
    float base1 = sgQ[cls * LATENT_ + tid];
    float acc = skb[tid];
    #pragma unroll 5
    for (int jf = 0; jf < NJF_; jf++) acc += xrow[jf] * skW[jf * LATENT_ + tid];

    float* dst = g_h + (size_t)r * DM_;
    {
        float ang = (float)(start + 0) * div;
        dst[tid]             = base0 + (odd ? cosf(ang) : sinf(ang));
    }
    {
        float ang = (float)(start + 1) * div;
        dst[tid + LATENT_]   = base1 + (odd ? cosf(ang) : sinf(ang));
    }
    {
        float ang = (float)(start + 2) * div;
        dst[tid + 2*LATENT_] = acc   + (odd ? cosf(ang) : sinf(ang));
    }
}

// ---------------------------------------------------------------------------
// fp32 SIMT GEMM: 32x64x16 tile, 256 threads, 2x4 per thread, double-buffered.
// act: 0 = none, 1 = elu(x)+1, 2 = relu
// ---------------------------------------------------------------------------
#define GBM 32
#define GBN 64
#define GBK 16

__device__ __forceinline__ void gemm_tile_body(const float* __restrict__ A,
                                               const float* __restrict__ B,
                                               const float* __restrict__ bias,
                                               float* __restrict__ C,
                                               int N, int K,
                                               int rowBase, int colBase, int act)
{
    __shared__ float As[2][GBM][20];   // row padded to 20 floats (16B-aligned float4)
    __shared__ float Bs[2][GBK][GBN];

    const int tid = threadIdx.x;
    const int tx  = tid & 15;          // 16 col groups * 4
    const int ty  = tid >> 4;          // 16 row groups * 2

    const bool aActive = tid < 128;
    const int  ar  = tid >> 2;         // 0..31
    const int  ac4 = (tid & 3) << 2;   // 0,4,8,12
    const int  br  = tid >> 4;         // 0..15
    const int  bc4 = (tid & 15) << 2;  // 0..60

    const float* Aptr = A + (size_t)(rowBase + ar) * K + ac4;
    const float* Bptr = B + (size_t)br * N + colBase + bc4;

    float acc[2][4] = {};
    float4 aReg, bReg;

    // preload tile 0
    if (aActive) aReg = *(const float4*)Aptr;
    bReg = *(const float4*)Bptr;
    if (aActive) *(float4*)&As[0][ar][ac4] = aReg;
    *(float4*)&Bs[0][br][bc4] = bReg;
    __syncthreads();

    const int KT = K / GBK;
    int buf = 0;
    for (int kt = 0; kt < KT; kt++) {
        const bool more = (kt + 1 < KT);
        if (more) {
            if (aActive) aReg = *(const float4*)(Aptr + (kt + 1) * GBK);
            bReg = *(const float4*)(Bptr + (size_t)(kt + 1) * GBK * N);
        }

        #pragma unroll
        for (int kk = 0; kk < GBK; kk++) {
            float a0 = As[buf][ty*2+0][kk];
            float a1 = As[buf][ty*2+1][kk];
            float4 bv = *(const float4*)&Bs[buf][kk][tx*4];
            acc[0][0] += a0*bv.x; acc[0][1] += a0*bv.y; acc[0][2] += a0*bv.z; acc[0][3] += a0*bv.w;
            acc[1][0] += a1*bv.x; acc[1][1] += a1*bv.y; acc[1][2] += a1*bv.z; acc[1][3] += a1*bv.w;
        }

        if (more) {
            if (aActive) *(float4*)&As[buf ^ 1][ar][ac4] = aReg;
            *(float4*)&Bs[buf ^ 1][br][bc4] = bReg;
        }
        __syncthreads();
        buf ^= 1;
    }

    const int c0 = colBase + tx * 4;
    float4 bsv = *(const float4*)(bias + c0);
    #pragma unroll
    for (int i = 0; i < 2; i++) {
        int r = rowBase + ty * 2 + i;
        float4 o;
        o.x = acc[i][0] + bsv.x;
        o.y = acc[i][1] + bsv.y;
        o.z = acc[i][2] + bsv.z;
        o.w = acc[i][3] + bsv.w;
        if (act == 1) {
            o.x = (o.x > 0.f) ? (o.x + 1.f) : expf(o.x);
            o.y = (o.y > 0.f) ? (o.y + 1.f) : expf(o.y);
            o.z = (o.z > 0.f) ? (o.z + 1.f) : expf(o.z);
            o.w = (o.w > 0.f) ? (o.w + 1.f) : expf(o.w);
        } else if (act == 2) {
            o.x = fmaxf(o.x, 0.f); o.y = fmaxf(o.y, 0.f);
            o.z = fmaxf(o.z, 0.f); o.w = fmaxf(o.w, 0.f);
        }
        *(float4*)(C + (size_t)r * N + c0) = o;
    }
}

__global__ void gemm_kernel(int a_code, const float* __restrict__ B,
                            const float* __restrict__ bias, int c_code,
                            int N, int K, int act)
{
    gemm_tile_body(scratch(a_code), B, bias, scratch(c_code),
                   N, K, blockIdx.y * GBM, blockIdx.x * GBN, act);
}

// Fused QKV: virtual N = 3*768; each 64-col block belongs to one matrix
__global__ void gemm_qkv_kernel(const float* __restrict__ Wq, const float* __restrict__ Wk,
                                const float* __restrict__ Wv,
                                const float* __restrict__ bq, const float* __restrict__ bk,
                                const float* __restrict__ bv)
{
    const int gcol = blockIdx.x * GBN;
    const int mat  = gcol / DM_;
    const int colBase = gcol - mat * DM_;
    const float* B    = (mat == 0) ? Wq  : (mat == 1) ? Wk  : Wv;
    const float* bias = (mat == 0) ? bq  : (mat == 1) ? bk  : bv;
    float*       C    = (mat == 0) ? g_q : (mat == 1) ? g_k : g_v;
    const int act     = (mat < 2) ? 1 : 0;   // elu+1 on Q,K; none on V
    gemm_tile_body(g_h, B, bias, C, DM_, DM_, blockIdx.y * GBM, colBase, act);
}

// ---------------------------------------------------------------------------
// Causal linear attention, tiled. Grid (chunk=4, bh=32); 256 threads.
// Each block: 20 query rows of one (b,h); K/V streamed through smem tiles.
// ---------------------------------------------------------------------------
#define CHUNK 20
#define ALD   193    // odd pad -> conflict-free strided smem reads

__global__ void attn_kernel()
{
    __shared__ float Qs [CHUNK][ALD];
    __shared__ float KVs[CHUNK][ALD];
    __shared__ float Asc[CHUNK][T_];
    __shared__ float inv[CHUNK];

    const int chunk = blockIdx.x;      // 0..3
    const int bh    = blockIdx.y;      // 0..31
    const int b  = bh >> 2;
    const int h  = bh & 3;
    const int t0 = chunk * CHUNK;
    const int tid = threadIdx.x;

    // stage Q chunk
    for (int i = tid; i < CHUNK * DH_; i += 256) {
        int tl = i / DH_, d = i - tl * DH_;
        Qs[tl][d] = g_q[(size_t)((t0 + tl) * BS_ + b) * DM_ + h * DH_ + d];
    }
    __syncthreads();

    // scores, tiled over tau
    for (int tt = 0; tt <= chunk; tt++) {
        const int tauBase = tt * CHUNK;
        for (int i = tid; i < CHUNK * DH_; i += 256) {
            int j = i / DH_, d = i - j * DH_;
            KVs[j][d] = g_k[(size_t)((tauBase + j) * BS_ + b) * DM_ + h * DH_ + d];
        }
        __syncthreads();

        for (int p = tid; p < CHUNK * CHUNK; p += 256) {
            int tl = p / CHUNK, tj = p - tl * CHUNK;
            float s = 0.0f;
            if (tauBase + tj <= t0 + tl) {
                #pragma unroll 8
                for (int d = 0; d < DH_; d++) s += Qs[tl][d] * KVs[tj][d];
            }
            Asc[tl][tauBase + tj] = s;
        }
        __syncthreads();
    }

    // 1 / (row-sum + eps) over the written width
    const int width = (chunk + 1) * CHUNK;
    if (tid < CHUNK) {
        float s = 0.0f;
        for (int tau = 0; tau < width; tau++) s += Asc[tid][tau];
        inv[tid] = 1.0f / (s + EPS_ATT);
    }
    __syncthreads();

    // AV, tiled over tau (masked scores are exact zeros)
    float acc[(CHUNK * DH_ + 255) / 256] = {};
    for (int tt = 0; tt <= chunk; tt++) {
        const int tauBase = tt * CHUNK;
        for (int i = tid; i < CHUNK * DH_; i += 256) {
            int j = i / DH_, d = i - j * DH_;
            KVs[j][d] = g_v[(size_t)((tauBase + j) * BS_ + b) * DM_ + h * DH_ + d];
        }
        __syncthreads();

        #pragma unroll
        for (int it = 0; it < (CHUNK * DH_ + 255) / 256; it++) {
            int idx = tid + it * 256;
            int tl = idx / DH_, d = idx - tl * DH_;
            float a = 0.0f;
            #pragma unroll
            for (int j = 0; j < CHUNK; j++) a += Asc[tl][tauBase + j] * KVs[j][d];
            acc[it] += a;
        }
        __syncthreads();
    }

    #pragma unroll
    for (int it = 0; it < (CHUNK * DH_ + 255) / 256; it++) {
        int idx = tid + it * 256;
        int tl = idx / DH_, d = idx - tl * DH_;
        g_att[(size_t)((t0 + tl) * BS_ + b) * DM_ + h * DH_ + d] = acc[it] * inv[tl];
    }
}

// ---------------------------------------------------------------------------
// LayerNorm helpers
// ---------------------------------------------------------------------------
__device__ __forceinline__ float block_sum_256(float val)
{
    __shared__ float sh[8];
    const int lane = threadIdx.x & 31;
    const int w    = threadIdx.x >> 5;
    #pragma unroll
    for (int o = 16; o > 0; o >>= 1) val += __shfl_down_sync(0xffffffffu, val, o);
    if (lane == 0) sh[w] = val;
    __syncthreads();
    if (w == 0) {
        float r = (lane < 8) ? sh[lane] : 0.0f;
        #pragma unroll
        for (int o = 4; o > 0; o >>= 1) r += __shfl_down_sync(0xffffffffu, r, o);
        if (lane == 0) sh[0] = r;
    }
    __syncthreads();
    float res = sh[0];
    __syncthreads();
    return res;
}

__global__ void ln_residual_kernel(int x_code, int y_code,
                                   const float* __restrict__ g, const float* __restrict__ bt,
                                   int out_code)
{
    const float* x  = scratch(x_code);
    const float* yv = scratch(y_code);
    float* out      = scratch(out_code);

    const int row = blockIdx.x;
    const int tid = threadIdx.x;
    const size_t base = (size_t)row * DM_;

    float v0 = x[base + tid]       + yv[base + tid];
    float v1 = x[base + tid + 256] + yv[base + tid + 256];
    float v2 = x[base + tid + 512] + yv[base + tid + 512];

    float mean = block_sum_256(v0 + v1 + v2) * (1.0f / (float)DM_);
    float d0 = v0 - mean, d1 = v1 - mean, d2 = v2 - mean;
    float var = block_sum_256(d0*d0 + d1*d1 + d2*d2) * (1.0f / (float)DM_);
    float rstd = rsqrtf(var + EPS_LN);

    out[base + tid]       = d0 * rstd * g[tid]       + bt[tid];
    out[base + tid + 256] = d1 * rstd * g[tid + 256] + bt[tid + 256];
    out[base + tid + 512] = d2 * rstd * g[tid + 512] + bt[tid + 512];
}

// ---------------------------------------------------------------------------
// Final: gather selected rows, final LN, emit mu || logvar
// ---------------------------------------------------------------------------
__global__ void gather_kernel(const int* __restrict__ act_ts,
                              const float* __restrict__ g, const float* __restrict__ bt,
                              float* __restrict__ out)
{
    const int ba = blockIdx.x;            // b*A + a
    const int b  = ba / A_;
    int t = act_ts[ba] - 1;
    if (t < 0) t = 0;
    const int row = t * BS_ + b;
    const int tid = threadIdx.x;
    const size_t base = (size_t)row * DM_;

    float v0 = g_h[base + tid];
    float v1 = g_h[base + tid + 256];
    float v2 = g_h[base + tid + 512];

    float mean = block_sum_256(v0 + v1 + v2) * (1.0f / (float)DM_);
    float d0 = v0 - mean, d1 = v1 - mean, d2 = v2 - mean;
    float var = block_sum_256(d0*d0 + d1*d1 + d2*d2) * (1.0f / (float)DM_);
    float rstd = rsqrtf(var + EPS_LN);

    out[(size_t)ba * LATENT_ + tid]                      = d0 * rstd * g[tid]       + bt[tid];
    out[(size_t)BS_ * A_ * LATENT_ + ba * LATENT_ + tid] = d1 * rstd * g[tid + 256] + bt[tid + 256];
}

// ---------------------------------------------------------------------------
// Host orchestration: kernel launches ONLY (graph-capture safe)
// ---------------------------------------------------------------------------
extern "C" void kernel_launch(void* const* d_in, const int* in_sizes, int n_in,
                              void* d_out, int out_size)
{
    const float* x    = (const float*)d_in[0];
    const int*   y    = (const int*)  d_in[1];
    const int*   ind  = (const int*)  d_in[2];
    const int*   ats  = (const int*)  d_in[3];
    const float* skW  = (const float*)d_in[4];
    const float* skb  = (const float*)d_in[5];
    const float* muQ  = (const float*)d_in[6];
    const float* sgQ  = (const float*)d_in[7];
    const float* Wq   = (const float*)d_in[8];
    const float* bq   = (const float*)d_in[9];
    const float* Wk   = (const float*)d_in[10];
    const float* bk   = (const float*)d_in[11];
    const float* Wv   = (const float*)d_in[12];
    const float* bv   = (const float*)d_in[13];
    const float* Wo   = (const float*)d_in[14];
    const float* bo   = (const float*)d_in[15];
    const float* W1   = (const float*)d_in[16];
    const float* b1   = (const float*)d_in[17];
    const float* W2   = (const float*)d_in[18];
    const float* b2   = (const float*)d_in[19];
    const float* l1g  = (const float*)d_in[20];
    const float* l1b  = (const float*)d_in[21];
    const float* l2g  = (const float*)d_in[22];
    const float* l2b  = (const float*)d_in[23];
    const float* lfg  = (const float*)d_in[24];
    const float* lfb  = (const float*)d_in[25];
    float* out = (float*)d_out;

    build_h0_kernel<<<ROWS_, 256>>>(x, y, ind, skW, skb, muQ, sgQ);

    const dim3 gQKV(3 * DM_ / GBN, ROWS_ / GBM);   // 36 x 20 = 720
    const dim3 g768(DM_ / GBN, ROWS_ / GBM);       // 12 x 20 = 240
    const dim3 g1024(FF_ / GBN, ROWS_ / GBM);      // 16 x 20 = 320
    const dim3 gAttn(4, BS_ * H_);                 // 4 chunks x 32 (b,h)

    for (int l = 0; l < L_; l++) {
        gemm_qkv_kernel<<<gQKV, 256>>>(Wq + (size_t)l * DM_ * DM_,
                                       Wk + (size_t)l * DM_ * DM_,
                                       Wv + (size_t)l * DM_ * DM_,
                                       bq + l * DM_, bk + l * DM_, bv + l * DM_);
        attn_kernel<<<gAttn, 256>>>();
        gemm_kernel<<<g768, 256>>>(BUF_ATT, Wo + (size_t)l * DM_ * DM_, bo + l * DM_,
                                   BUF_Q, DM_, DM_, 0);
        ln_residual_kernel<<<ROWS_, 256>>>(BUF_H, BUF_Q, l1g + l * DM_, l1b + l * DM_, BUF_H1);
        gemm_kernel<<<g1024, 256>>>(BUF_H1, W1 + (size_t)l * DM_ * FF_, b1 + l * FF_,
                                    BUF_FF, FF_, DM_, 2);
        gemm_kernel<<<g768, 256>>>(BUF_FF, W2 + (size_t)l * FF_ * DM_, b2 + l * DM_,
                                   BUF_Q, DM_, FF_, 0);
        ln_residual_kernel<<<ROWS_, 256>>>(BUF_H1, BUF_Q, l2g + l * DM_, l2b + l * DM_, BUF_H);
    }

    gather_kernel<<<BS_ * A_, 256>>>(ats, lfg, lfb, out);
}